// round 8
// baseline (speedup 1.0000x reference)
#include <cuda_runtime.h>
#include <cstdint>

// SINDy library: out[row] = [1, z(32), z_i*z_j (528), z_a*z_b*z_c (5984), sin(z)(32)]
// 8192 rows x 6577 cols fp32. value(col) = s_mul[a] * s_buf[k]; s_mul[32]=1.0 makes
// non-triple regions use the same uniform path.
// R8: persistent blocks (grid=592, ~14 rows each, phase-invariant), double-buffered
// row state with z prefetch + deferred build -> hide per-row prologue latency.

#define NDIM     32
#define NPAIRS   528
#define NCOLS    6577
#define SBUF_PAD 600
#define NTHREADS 512
#define NBLOCKS  592           // 4 per SM x 148 SMs; 592 % 4 == 0 keeps phase constant
#define NROWS    8192
#define TB_PAD   2176          // >= max ng (1644) + NTHREADS pad

static constexpr int pair_index(int i, int j) {
    return i * NDIM - (i * (i - 1)) / 2 + (j - i);
}

struct ColTbl { unsigned short e[NCOLS]; };   // per column: k | (a<<10)

static constexpr ColTbl make_col_tbl() {
    ColTbl t{};
    for (int c = 0; c < 561; ++c)                       // 1, z, pairs: k=c, a=32 (=1.0)
        t.e[c] = (unsigned short)((unsigned)c | (32u << 10));
    {
        int col = 561;                                  // triples
        for (int a = 0; a < NDIM; ++a)
            for (int b = a; b < NDIM; ++b)
                for (int c = b; c < NDIM; ++c) {
                    unsigned k = 33u + (unsigned)pair_index(b, c);
                    t.e[col++] = (unsigned short)(k | ((unsigned)a << 10));
                }
    }
    for (int i = 0; i < NDIM; ++i)                      // sin: k = 561+i, a=32
        t.e[6545 + i] = (unsigned short)((unsigned)(561 + i) | (32u << 10));
    return t;
}
__device__ constexpr ColTbl G_COL = make_col_tbl();

// Per phase ph = (-row)&3, per 4-col group g (c0 = ph + 4g):
//   uniform:  low16 = byte offset into s_copy[buf] (copy picked for 16B alignment),
//             bits[16..30) = a*4 (byte offset into s_mul; a=32 -> 1.0f)
//   boundary: bit31 set (low16 = 0 -> safe dummy LDS).
struct Tbl4 {
    unsigned e[4][TB_PAD];
    int      ng[4];
};

static constexpr Tbl4 make_tbl4() {
    ColTbl ct = make_col_tbl();
    Tbl4 t{};
    for (int ph = 0; ph < 4; ++ph) {
        int ng = (NCOLS - ph) / 4;
        t.ng[ph] = ng;
        for (int g = 0; g < ng; ++g) {
            int c0 = ph + 4 * g;
            unsigned k0 = ct.e[c0] & 1023u;
            unsigned a0 = (unsigned)(ct.e[c0] >> 10);
            bool uniform = true;
            for (int j = 1; j < 4; ++j) {
                unsigned kj = ct.e[c0 + j] & 1023u;
                unsigned aj = (unsigned)(ct.e[c0 + j] >> 10);
                if (kj != k0 + (unsigned)j || aj != a0) { uniform = false; break; }
            }
            if (uniform) {
                unsigned P   = (4u - (k0 & 3u)) & 3u;
                unsigned off = (P * SBUF_PAD + k0 + P) * 4u;
                t.e[ph][g] = off | ((a0 * 4u) << 16);
            } else {
                t.e[ph][g] = 0x80000000u;
            }
        }
        for (int g = ng; g < TB_PAD; ++g) t.e[ph][g] = 0;  // prefetch pad
    }
    return t;
}
__device__ constexpr Tbl4 G4 = make_tbl4();

struct PairTbl { unsigned short e[NPAIRS]; };
static constexpr PairTbl make_pair_tbl() {
    PairTbl t{};
    int p = 0;
    for (int i = 0; i < NDIM; ++i)
        for (int j = i; j < NDIM; ++j)
            t.e[p++] = (unsigned short)((unsigned)i | ((unsigned)j << 8));
    return t;
}
__device__ constexpr PairTbl G_PAIR = make_pair_tbl();

__global__ __launch_bounds__(NTHREADS) void sindy_library_kernel(
    const float* __restrict__ z, float* __restrict__ out)
{
    // Double-buffered row state. s_copy[buf][P][P+k] = buf[k]; LDS.128 at (k0+P),
    // P=(-k0)&3, is 16B-aligned and conflict-free.
    __shared__ __align__(16) float s_copy[2][4][SBUF_PAD];
    __shared__ float s_mul[2][NDIM + 1];   // z..., 1.0f at [32]

    const int t = threadIdx.x;
    int row = blockIdx.x;
    const int ph = (4 - (row & 3)) & 3;    // invariant: rows step by 592 (mult of 4)

    // ---- cold prologue: build buffer 0 for the first row ----
    float zv = 0.0f;
    if (t < NDIM) zv = z[row * NDIM + t];
    if (t < NDIM) {
        float sv = __sinf(zv);
        s_mul[0][t] = zv;
        #pragma unroll
        for (int P = 0; P < 4; ++P) {
            s_copy[0][P][P + 1 + t]   = zv;
            s_copy[0][P][P + 561 + t] = sv;
        }
    } else if (t == NDIM) {
        s_mul[0][NDIM] = 1.0f;
        #pragma unroll
        for (int P = 0; P < 4; ++P) s_copy[0][P][P] = 1.0f;
    }
    __syncthreads();
    for (int p = t; p < NPAIRS; p += NTHREADS) {
        unsigned ij = (unsigned)G_PAIR.e[p];
        float v = s_mul[0][ij & 31u] * s_mul[0][(ij >> 8) & 31u];
        #pragma unroll
        for (int P = 0; P < 4; ++P) s_copy[0][P][P + 33 + p] = v;
    }
    __syncthreads();

    const int ng = G4.ng[ph];
    const unsigned* __restrict__ tb = &G4.e[ph][0];

    int cur = 0;
    while (row < NROWS) {
        const int nrow = row + NBLOCKS;

        // Prefetch next row's z into registers (latency hidden behind main loop).
        if (t < NDIM) zv = (nrow < NROWS) ? z[nrow * NDIM + t] : 0.0f;

        float* __restrict__ o = out + (size_t)row * NCOLS;
        const char* __restrict__ sc = (const char*)&s_copy[cur][0][0];
        const char* __restrict__ sm = (const char*)&s_mul[cur][0];

        // Head scalars (< 4 cols)
        if (t < ph) {
            unsigned e = (unsigned)G_COL.e[t];
            o[t] = s_mul[cur][e >> 10] * s_copy[cur][0][e & 1023u];
        }

        unsigned e = __ldg(&tb[t]);
        for (int g = t; g < ng; g += NTHREADS) {
            unsigned en = __ldg(&tb[g + NTHREADS]);   // padded: always in-bounds

            float4 b  = *(const float4*)(sc + (e & 0xFFFFu));
            float  za = *(const float*)(sm + ((e >> 16) & 0x3FFFu));
            float4 r  = make_float4(za * b.x, za * b.y, za * b.z, za * b.w);

            if ((int)e < 0) {                         // rare boundary group (~2%)
                const int c0 = ph + 4 * g;
                unsigned e0 = (unsigned)G_COL.e[c0];
                unsigned e1 = (unsigned)G_COL.e[c0 + 1];
                unsigned e2 = (unsigned)G_COL.e[c0 + 2];
                unsigned e3 = (unsigned)G_COL.e[c0 + 3];
                r.x = s_mul[cur][e0 >> 10] * s_copy[cur][0][e0 & 1023u];
                r.y = s_mul[cur][e1 >> 10] * s_copy[cur][0][e1 & 1023u];
                r.z = s_mul[cur][e2 >> 10] * s_copy[cur][0][e2 & 1023u];
                r.w = s_mul[cur][e3 >> 10] * s_copy[cur][0][e3 & 1023u];
            }

            __stcs((float4*)(o + ph + 4 * g), r);
            e = en;
        }

        // Tail scalars (< 4 cols)
        {
            int c = ph + 4 * ng + t;
            if (c < NCOLS) {
                unsigned ee = (unsigned)G_COL.e[c];
                o[c] = s_mul[cur][ee >> 10] * s_copy[cur][0][ee & 1023u];
            }
        }

        // ---- build next row's buffer (overlaps store drain of this row) ----
        const int nxt = cur ^ 1;
        if (t < NDIM) {
            float sv = __sinf(zv);
            s_mul[nxt][t] = zv;
            #pragma unroll
            for (int P = 0; P < 4; ++P) {
                s_copy[nxt][P][P + 1 + t]   = zv;
                s_copy[nxt][P][P + 561 + t] = sv;
            }
        } else if (t == NDIM) {
            s_mul[nxt][NDIM] = 1.0f;
            #pragma unroll
            for (int P = 0; P < 4; ++P) s_copy[nxt][P][P] = 1.0f;
        }
        __syncthreads();          // z[nxt] visible for pair build
        for (int p = t; p < NPAIRS; p += NTHREADS) {
            unsigned ij = (unsigned)G_PAIR.e[p];
            float v = s_mul[nxt][ij & 31u] * s_mul[nxt][(ij >> 8) & 31u];
            #pragma unroll
            for (int P = 0; P < 4; ++P) s_copy[nxt][P][P + 33 + p] = v;
        }
        __syncthreads();          // buf[nxt] complete; also fences cur for reuse
        cur = nxt;
        row = nrow;
    }
}

extern "C" void kernel_launch(void* const* d_in, const int* in_sizes, int n_in,
                              void* d_out, int out_size) {
    const float* z   = (const float*)d_in[0];
    float*       out = (float*)d_out;
    sindy_library_kernel<<<NBLOCKS, NTHREADS>>>(z, out);
}